// round 12
// baseline (speedup 1.0000x reference)
#include <cuda_runtime.h>
#include <math.h>

#define BATCH 8
#define LSEQ  1024
#define BL    8192
#define DM    256
#define DIN   512
#define DPROJ 1160
#define CONVD 640
#define NH    8
#define HD    64
#define DS    64

// ---------------- scratch (device globals; no runtime allocation) ------------
__device__ float g_zx[BL * DPROJ];    // in_proj output (zxbcdt)     ~38 MB
__device__ float g_xbc[BL * CONVD];   // conv+silu output            ~21 MB
__device__ float g_dt[BL * NH];
__device__ float g_dA[BL * NH];
__device__ float g_ypre[BL * DIN];    // scan output incl. D*x       ~17 MB
__device__ float g_ynorm[BL * DIN];   // gated + rmsnormed
__device__ float g_h[BL * DM];        // hidden between the 2 blocks

// ---------------- SGEMM: C[M,N] = A[M,K] * W[N,K]^T  (both K-contiguous) -----
__global__ __launch_bounds__(256) void sgemm_nt(
    const float* __restrict__ A, const float* __restrict__ W,
    float* __restrict__ C, int M, int N, int K) {
  __shared__ float As[16][128];
  __shared__ float Ws[16][128];
  const int tid = threadIdx.x;
  const int tx = tid & 15;        // n-dir
  const int ty = tid >> 4;        // m-dir
  const int m0 = blockIdx.y * 128;
  const int n0 = blockIdx.x * 128;
  const int lr = tid >> 2;        // 0..63 row for loads
  const int lc = (tid & 3) * 4;   // 0,4,8,12 col for loads

  float acc[8][8];
#pragma unroll
  for (int i = 0; i < 8; i++)
#pragma unroll
    for (int j = 0; j < 8; j++) acc[i][j] = 0.f;

  for (int k0 = 0; k0 < K; k0 += 16) {
#pragma unroll
    for (int rr = 0; rr < 2; rr++) {
      int m = m0 + lr + rr * 64;
      float4 v = *reinterpret_cast<const float4*>(A + (size_t)m * K + k0 + lc);
      As[lc + 0][lr + rr * 64] = v.x;
      As[lc + 1][lr + rr * 64] = v.y;
      As[lc + 2][lr + rr * 64] = v.z;
      As[lc + 3][lr + rr * 64] = v.w;
    }
#pragma unroll
    for (int rr = 0; rr < 2; rr++) {
      int n = n0 + lr + rr * 64;
      float4 v = make_float4(0.f, 0.f, 0.f, 0.f);
      if (n < N)
        v = *reinterpret_cast<const float4*>(W + (size_t)n * K + k0 + lc);
      Ws[lc + 0][lr + rr * 64] = v.x;
      Ws[lc + 1][lr + rr * 64] = v.y;
      Ws[lc + 2][lr + rr * 64] = v.z;
      Ws[lc + 3][lr + rr * 64] = v.w;
    }
    __syncthreads();
#pragma unroll
    for (int kk = 0; kk < 16; kk++) {
      float a[8], b[8];
      *reinterpret_cast<float4*>(&a[0]) = *reinterpret_cast<const float4*>(&As[kk][ty * 8]);
      *reinterpret_cast<float4*>(&a[4]) = *reinterpret_cast<const float4*>(&As[kk][ty * 8 + 4]);
      *reinterpret_cast<float4*>(&b[0]) = *reinterpret_cast<const float4*>(&Ws[kk][tx * 8]);
      *reinterpret_cast<float4*>(&b[4]) = *reinterpret_cast<const float4*>(&Ws[kk][tx * 8 + 4]);
#pragma unroll
      for (int i = 0; i < 8; i++)
#pragma unroll
        for (int j = 0; j < 8; j++)
          acc[i][j] = fmaf(a[i], b[j], acc[i][j]);
    }
    __syncthreads();
  }

#pragma unroll
  for (int i = 0; i < 8; i++) {
    int m = m0 + ty * 8 + i;
    float* crow = C + (size_t)m * N;
#pragma unroll
    for (int j4 = 0; j4 < 8; j4 += 4) {
      int n = n0 + tx * 8 + j4;
      if (n < N) {
        float4 v = make_float4(acc[i][j4], acc[i][j4 + 1], acc[i][j4 + 2], acc[i][j4 + 3]);
        *reinterpret_cast<float4*>(crow + n) = v;
      }
    }
  }
}

// ---------------- depthwise causal conv(4) + bias + silu ---------------------
__global__ __launch_bounds__(128) void conv_silu_kernel(
    const float* __restrict__ zx, const float* __restrict__ cw,
    const float* __restrict__ cb, float* __restrict__ out) {
  const int c  = blockIdx.y * 128 + threadIdx.x;   // 0..639
  const int b  = blockIdx.z;
  const int l0 = blockIdx.x * 128;
  const float w0 = cw[c * 4 + 0], w1 = cw[c * 4 + 1];
  const float w2 = cw[c * 4 + 2], w3 = cw[c * 4 + 3];
  const float bias = cb[c];
  const float* src = zx + (size_t)b * LSEQ * DPROJ + DIN + c;
  float* dst = out + (size_t)b * LSEQ * CONVD + c;
  float x0 = 0.f, x1 = 0.f, x2 = 0.f;
  if (l0 > 0) {
    x0 = src[(size_t)(l0 - 3) * DPROJ];
    x1 = src[(size_t)(l0 - 2) * DPROJ];
    x2 = src[(size_t)(l0 - 1) * DPROJ];
  }
  for (int l = l0; l < l0 + 128; l++) {
    float xc = src[(size_t)l * DPROJ];
    float v = fmaf(w0, x0, fmaf(w1, x1, fmaf(w2, x2, fmaf(w3, xc, bias))));
    v = __fdividef(v, 1.f + __expf(-v));       // silu (fast path)
    dst[(size_t)l * CONVD] = v;
    x0 = x1; x1 = x2; x2 = xc;
  }
}

// ---------------- dt = softplus(raw + bias);  dA = exp(dt * A) ---------------
__global__ __launch_bounds__(256) void dt_dA_kernel(
    const float* __restrict__ zx, const float* __restrict__ dtb,
    const float* __restrict__ alog, float* __restrict__ dt_out,
    float* __restrict__ dA_out) {
  int idx = blockIdx.x * 256 + threadIdx.x;   // < BL*NH
  if (idx >= BL * NH) return;
  int hh = idx & 7;
  int row = idx >> 3;
  float raw = zx[(size_t)row * DPROJ + (DPROJ - NH) + hh] + dtb[hh];
  float dtv = raw > 20.f ? raw : log1pf(__expf(raw));
  float A = -__expf(alog[hh]);
  dt_out[idx] = dtv;
  dA_out[idx] = __expf(dtv * A);
}

// ---------------- SSM scan (STS-partials version, no shuffle chain) ----------
// grid (64 = b*h, 4 = p-quarter), 256 threads.
// thread t: pl = t>>4 (16 p rows), nl = t&15, 4 states at n0 = nl*4.
// Per 16-step chunk: main loop stores per-lane y partials to smem (STS,
// no latency chain), then a parallel reduction pass sums over nl and writes
// y (+ D*x skip) straight to gmem. Removes the 4-deep SHFL chain that bounded
// previous rounds.
#define CH 16
__global__ __launch_bounds__(256) void scan_kernel(
    const float* __restrict__ xbc, const float* __restrict__ dt,
    const float* __restrict__ dA, const float* __restrict__ Dp,
    float* __restrict__ ypre) {
  const int bh = blockIdx.x;
  const int b = bh >> 3, h = bh & 7;
  const int p0 = blockIdx.y * 16;
  const int t = threadIdx.x;
  const int pl = t >> 4;          // 0..15 : p row within block
  const int nl = t & 15;          // 0..15 : n lane group
  const int n0 = nl * 4;
  const float Dh = Dp[h];

  __shared__ float sx[CH][16];             // raw x values (for D skip too)
  __shared__ float sB[CH][64];
  __shared__ float sC[CH][64];
  __shared__ float2 sdtda[CH];             // (dt, dA)
  __shared__ float ypart[CH][16][16];      // [l][pl][nl] partials  (16KB)

  float s[4];
#pragma unroll
  for (int k = 0; k < 4; k++) s[k] = 0.f;

  const size_t row0 = (size_t)b * LSEQ;
  for (int l0 = 0; l0 < LSEQ; l0 += CH) {
    // -------- stage chunk --------
    {
      // sx: 16x16 = 256 elems, one per thread
      int r = t >> 4, cc = t & 15;
      sx[r][cc] = xbc[(row0 + l0 + r) * CONVD + h * HD + p0 + cc];
    }
    for (int i = t; i < CH * 64; i += 256) {
      int r = i >> 6, cc = i & 63;
      sB[r][cc] = xbc[(row0 + l0 + r) * CONVD + DIN + cc];
      sC[r][cc] = xbc[(row0 + l0 + r) * CONVD + DIN + DS + cc];
    }
    if (t < CH) {
      sdtda[t] = make_float2(dt[(row0 + l0 + t) * NH + h],
                             dA[(row0 + l0 + t) * NH + h]);
    }
    __syncthreads();

    // -------- recurrence: 16 steps, partials to smem --------
#pragma unroll
    for (int l = 0; l < CH; l++) {
      float2 da = sdtda[l];
      float coef = da.x * sx[l][pl];
      float4 Bv = *reinterpret_cast<const float4*>(&sB[l][n0]);
      float4 Cv = *reinterpret_cast<const float4*>(&sC[l][n0]);
      float yp0, yp1;
      s[0] = fmaf(s[0], da.y, coef * Bv.x);
      s[1] = fmaf(s[1], da.y, coef * Bv.y);
      s[2] = fmaf(s[2], da.y, coef * Bv.z);
      s[3] = fmaf(s[3], da.y, coef * Bv.w);
      yp0 = s[0] * Cv.x;
      yp1 = s[1] * Cv.y;
      yp0 = fmaf(s[2], Cv.z, yp0);
      yp1 = fmaf(s[3], Cv.w, yp1);
      ypart[l][pl][nl] = yp0 + yp1;
    }
    __syncthreads();

    // -------- reduction pass: sum over nl, add D*x, write to gmem --------
    {
      int l = t >> 4, pp = t & 15;       // one output per thread
      const float4* pb = reinterpret_cast<const float4*>(&ypart[l][pp][0]);
      float4 a0 = pb[0], a1 = pb[1], a2 = pb[2], a3 = pb[3];
      float sum = ((a0.x + a0.y) + (a0.z + a0.w))
                + ((a1.x + a1.y) + (a1.z + a1.w))
                + ((a2.x + a2.y) + (a2.z + a2.w))
                + ((a3.x + a3.y) + (a3.z + a3.w));
      sum = fmaf(Dh, sx[l][pp], sum);
      ypre[(row0 + l0 + l) * DIN + h * HD + p0 + pp] = sum;
    }
    __syncthreads();
  }
}

// ---------------- y = (ypre * silu(z)), RMSnorm over 512, * norm_w -----------
__global__ __launch_bounds__(128) void gate_norm_kernel(
    const float* __restrict__ ypre, const float* __restrict__ zx,
    const float* __restrict__ nw, float* __restrict__ out) {
  const int row = blockIdx.x;     // 8192
  const int t = threadIdx.x;      // 128
  float v[4];
  float ss = 0.f;
#pragma unroll
  for (int i = 0; i < 4; i++) {
    int c = t + i * 128;
    float y = ypre[(size_t)row * DIN + c];
    float z = zx[(size_t)row * DPROJ + c];
    float g = __fdividef(z, 1.f + __expf(-z));
    float val = y * g;
    v[i] = val;
    ss += val * val;
  }
#pragma unroll
  for (int o = 16; o > 0; o >>= 1) ss += __shfl_down_sync(0xffffffffu, ss, o);
  __shared__ float ws[4];
  if ((t & 31) == 0) ws[t >> 5] = ss;
  __syncthreads();
  float tot = ws[0] + ws[1] + ws[2] + ws[3];
  float scale = rsqrtf(tot * (1.f / 512.f) + 1e-5f);
#pragma unroll
  for (int i = 0; i < 4; i++) {
    int c = t + i * 128;
    out[(size_t)row * DIN + c] = v[i] * scale * nw[c];
  }
}

// ---------------- launch ----------------------------------------------------
extern "C" void kernel_launch(void* const* d_in, const int* in_sizes, int n_in,
                              void* d_out, int out_size) {
  const float* x    = (const float*)d_in[0];  // (8,32,32,256) == (8192,256)
  const float* wi   = (const float*)d_in[1];  // (2,1160,256)
  const float* cw   = (const float*)d_in[2];  // (2,640,1,4)
  const float* cb   = (const float*)d_in[3];  // (2,640)
  const float* dtb  = (const float*)d_in[4];  // (2,8)
  const float* alog = (const float*)d_in[5];  // (2,8)
  const float* Dp   = (const float*)d_in[6];  // (2,8)
  const float* nw   = (const float*)d_in[7];  // (2,512)
  const float* wo   = (const float*)d_in[8];  // (2,256,512)
  float* out = (float*)d_out;

  float *p_zx, *p_xbc, *p_dt, *p_dA, *p_ypre, *p_ynorm, *p_h;
  cudaGetSymbolAddress((void**)&p_zx, g_zx);
  cudaGetSymbolAddress((void**)&p_xbc, g_xbc);
  cudaGetSymbolAddress((void**)&p_dt, g_dt);
  cudaGetSymbolAddress((void**)&p_dA, g_dA);
  cudaGetSymbolAddress((void**)&p_ypre, g_ypre);
  cudaGetSymbolAddress((void**)&p_ynorm, g_ynorm);
  cudaGetSymbolAddress((void**)&p_h, g_h);

  for (int i = 0; i < 2; i++) {
    const float* hin = (i == 0) ? x : p_h;
    float* hout = (i == 1) ? out : p_h;

    // in_proj: (8192,1160) = h (8192,256) @ wi^T
    sgemm_nt<<<dim3((DPROJ + 127) / 128, BL / 128), 256>>>(
        hin, wi + (size_t)i * DPROJ * DM, p_zx, BL, DPROJ, DM);

    // conv + silu on xBC channels
    conv_silu_kernel<<<dim3(LSEQ / 128, CONVD / 128, BATCH), 128>>>(
        p_zx, cw + (size_t)i * CONVD * 4, cb + (size_t)i * CONVD, p_xbc);

    // dt / dA
    dt_dA_kernel<<<(BL * NH + 255) / 256, 256>>>(
        p_zx, dtb + i * NH, alog + i * NH, p_dt, p_dA);

    // SSM scan (+ D*x skip): 4-way p split, STS-partials reduction
    scan_kernel<<<dim3(BATCH * NH, 4), 256>>>(
        p_xbc, p_dt, p_dA, Dp + i * NH, p_ypre);

    // gate by silu(z), RMSnorm, * norm_w
    gate_norm_kernel<<<BL, 128>>>(p_ypre, p_zx, nw + (size_t)i * DIN, p_ynorm);

    // out_proj: (8192,256) = ynorm (8192,512) @ wo^T
    sgemm_nt<<<dim3(DM / 128, BL / 128), 256>>>(
        p_ynorm, wo + (size_t)i * DM * DIN, hout, BL, DM, DIN);
  }
}